// round 3
// baseline (speedup 1.0000x reference)
#include <cuda_runtime.h>
#include <cuda_bf16.h>
#include <math_constants.h>

#define VV 3
#define BB 2
#define CC 16
#define HH 128
#define WW 128
#define DD 32
#define HWSZ (HH*WW)
#define NQ 4                       // 16 channels as 4 x float4 chunks

// Scratch (device globals; no runtime allocation)
__device__ float g_proj[(VV-1)*BB*12];
// channel-chunk-planar features: index (vb*NQ + q)*HWSZ + pix
__device__ float4 g_feat[(size_t)VV*BB*NQ*HWSZ];
__device__ float g_cost[(size_t)BB*DD*HWSZ];           // min cost volume (b,d,pix)
__device__ float g_wfeat[(size_t)25*BB*HWSZ];          // feature weights [k][b][pix]
__device__ float g_agg[(size_t)BB*DD*HWSZ];            // aggregated costs (b,d,pix)

// ---------------------------------------------------------------------------
// K0: projection matrices  proj = M_src @ inv(M_ref)
// ---------------------------------------------------------------------------
__device__ void mat3_inv_d(const double* A, double* o) {
    double c00 = A[4]*A[8]-A[5]*A[7];
    double c01 = A[5]*A[6]-A[3]*A[8];
    double c02 = A[3]*A[7]-A[4]*A[6];
    double det = A[0]*c00 + A[1]*c01 + A[2]*c02;
    double id = 1.0/det;
    o[0]=c00*id;                  o[1]=(A[2]*A[7]-A[1]*A[8])*id; o[2]=(A[1]*A[5]-A[2]*A[4])*id;
    o[3]=c01*id;                  o[4]=(A[0]*A[8]-A[2]*A[6])*id; o[5]=(A[2]*A[3]-A[0]*A[5])*id;
    o[6]=c02*id;                  o[7]=(A[1]*A[6]-A[0]*A[7])*id; o[8]=(A[0]*A[4]-A[1]*A[3])*id;
}

__device__ void build_M(const float* intr, const float* c2w, int vb,
                        double* Afull, double* bfull) {
    double K[9], R[9], t[3];
    #pragma unroll
    for (int i = 0; i < 3; i++) {
        #pragma unroll
        for (int j = 0; j < 3; j++) {
            K[i*3+j] = (double)intr[(vb*3+i)*3+j];
            R[i*3+j] = (double)c2w[(vb*4+i)*4+j];
        }
        t[i] = (double)c2w[(vb*4+i)*4+3];
    }
    double bb[3];
    #pragma unroll
    for (int i = 0; i < 3; i++)
        bb[i] = -(R[0*3+i]*t[0] + R[1*3+i]*t[1] + R[2*3+i]*t[2]);
    #pragma unroll
    for (int i = 0; i < 3; i++) {
        #pragma unroll
        for (int j = 0; j < 3; j++)
            Afull[i*3+j] = K[i*3+0]*R[j*3+0] + K[i*3+1]*R[j*3+1] + K[i*3+2]*R[j*3+2];
        bfull[i] = K[i*3+0]*bb[0] + K[i*3+1]*bb[1] + K[i*3+2]*bb[2] + bb[i];
    }
}

__global__ void proj_kernel(const float* __restrict__ intr,
                            const float* __restrict__ c2w) {
    int t = threadIdx.x;
    if (t >= (VV-1)*BB) return;
    int v = t / BB + 1;
    int b = t % BB;

    double As[9], bs[3], Ar[9], br[3];
    build_M(intr, c2w, v*BB + b, As, bs);
    build_M(intr, c2w, 0*BB + b, Ar, br);

    double Ainv[9];
    mat3_inv_d(Ar, Ainv);
    double binv[3];
    #pragma unroll
    for (int i = 0; i < 3; i++)
        binv[i] = -(Ainv[i*3+0]*br[0] + Ainv[i*3+1]*br[1] + Ainv[i*3+2]*br[2]);

    float* P = g_proj + t*12;
    #pragma unroll
    for (int i = 0; i < 3; i++) {
        #pragma unroll
        for (int j = 0; j < 3; j++)
            P[i*3+j] = (float)(As[i*3+0]*Ainv[0*3+j] + As[i*3+1]*Ainv[1*3+j] + As[i*3+2]*Ainv[2*3+j]);
        P[9+i] = (float)(As[i*3+0]*binv[0] + As[i*3+1]*binv[1] + As[i*3+2]*binv[2] + bs[i]);
    }
}

// ---------------------------------------------------------------------------
// K1: transpose features (V,B,C,H,W) -> chunk-planar (vb, q, pix) float4
// ---------------------------------------------------------------------------
__global__ void nhwc_kernel(const float* __restrict__ feat) {
    int idx = blockIdx.x * blockDim.x + threadIdx.x;
    if (idx >= VV*BB*HWSZ) return;
    int pix = idx & (HWSZ-1);
    int vb  = idx >> 14;
    const float* in = feat + (size_t)vb*CC*HWSZ + pix;
    #pragma unroll
    for (int q = 0; q < NQ; q++) {
        float4 v;
        v.x = in[(size_t)(q*4+0)*HWSZ];
        v.y = in[(size_t)(q*4+1)*HWSZ];
        v.z = in[(size_t)(q*4+2)*HWSZ];
        v.w = in[(size_t)(q*4+3)*HWSZ];
        g_feat[((size_t)(vb*NQ + q))*HWSZ + pix] = v;   // coalesced per q
    }
}

// ---------------------------------------------------------------------------
// K2: homography warp + bilinear sample + cumsum cost + min over views
// ---------------------------------------------------------------------------
__global__ void __launch_bounds__(256)
warp_cost_kernel(const float* __restrict__ depth_hypo) {
    int idx = blockIdx.x * blockDim.x + threadIdx.x;
    if (idx >= BB*DD*HWSZ) return;
    int x = idx & 127;
    int y = (idx >> 7) & 127;
    int b = idx >> 19;
    int pix = idx & (HWSZ-1);

    float depth = depth_hypo[idx];

    // ref features (view 0, batch b): 4 contiguous float4 planes
    float rv[16];
    #pragma unroll
    for (int q = 0; q < NQ; q++) {
        float4 r = g_feat[((size_t)(b*NQ + q))*HWSZ + pix];
        rv[q*4+0] = r.x; rv[q*4+1] = r.y; rv[q*4+2] = r.z; rv[q*4+3] = r.w;
    }

    float cum[16];
    #pragma unroll
    for (int c = 0; c < 16; c++) cum[c] = 0.0f;

    const float SXY = (float)WW / (float)(WW-1);
    float fxp = (float)x, fyp = (float)y;
    float cost_min = CUDART_INF_F;

    #pragma unroll
    for (int v = 0; v < VV-1; v++) {
        const float* P = g_proj + (v*BB + b)*12;
        float X = (P[0]*fxp + P[1]*fyp + P[2])*depth + P[9];
        float Y = (P[3]*fxp + P[4]*fyp + P[5])*depth + P[10];
        float Z = (P[6]*fxp + P[7]*fyp + P[8])*depth + P[11];
        float px = __fdividef(X, Z) * SXY - 0.5f;
        float py = __fdividef(Y, Z) * SXY - 0.5f;
        float x0f = floorf(px), y0f = floorf(py);
        float tx = px - x0f, ty = py - y0f;
        int x0 = (int)x0f, y0 = (int)y0f;

        float w00 = (1.0f-tx)*(1.0f-ty);
        float w01 = tx*(1.0f-ty);
        float w10 = (1.0f-tx)*ty;
        float w11 = tx*ty;

        int svb = (v+1)*BB + b;

        int xs[4] = {x0, x0+1, x0, x0+1};
        int ys[4] = {y0, y0, y0+1, y0+1};
        float ws[4] = {w00, w01, w10, w11};
        #pragma unroll
        for (int tap = 0; tap < 4; tap++) {
            int xi = xs[tap], yi = ys[tap];
            if ((unsigned)xi < (unsigned)WW && (unsigned)yi < (unsigned)HH) {
                int sp = (yi<<7) + xi;
                float w = ws[tap];
                #pragma unroll
                for (int q = 0; q < NQ; q++) {
                    float4 a = g_feat[((size_t)(svb*NQ + q))*HWSZ + sp];
                    cum[q*4+0] += w*a.x; cum[q*4+1] += w*a.y;
                    cum[q*4+2] += w*a.z; cum[q*4+3] += w*a.w;
                }
            }
        }

        float s = 0.0f;
        #pragma unroll
        for (int c = 0; c < 16; c++) {
            float dlt = rv[c] - cum[c];
            s += dlt*dlt;
        }
        cost_min = fminf(cost_min, sqrtf(s));
    }
    g_cost[idx] = cost_min;
}

// ---------------------------------------------------------------------------
// K3a: feature weights per (k, b, pix):  wfeat = ||f_nb - f_c||
// ---------------------------------------------------------------------------
__global__ void __launch_bounds__(256)
wfeat_kernel() {
    int idx = blockIdx.x * blockDim.x + threadIdx.x;   // over 25*B*HWSZ
    if (idx >= 25*BB*HWSZ) return;
    int pix = idx & (HWSZ-1);
    int b   = (idx >> 14) & (BB-1);
    int k   = idx >> 15;
    int x = pix & 127;
    int y = pix >> 7;
    int ny = y + k/5 - 2, nx = x + k%5 - 2;

    float w = 0.0f;
    if ((unsigned)ny < (unsigned)HH && (unsigned)nx < (unsigned)WW) {
        int np = (ny<<7) + nx;
        float s = 0.0f;
        #pragma unroll
        for (int q = 0; q < NQ; q++) {
            float4 a = g_feat[((size_t)(b*NQ + q))*HWSZ + pix];
            float4 c = g_feat[((size_t)(b*NQ + q))*HWSZ + np];
            float d0 = a.x-c.x, d1 = a.y-c.y, d2 = a.z-c.z, d3 = a.w-c.w;
            s += d0*d0 + d1*d1 + d2*d2 + d3*d3;
        }
        w = sqrtf(s);
    }
    g_wfeat[idx] = w;
}

// ---------------------------------------------------------------------------
// K3b: per-(b,d,pix) neighborhood aggregation with depth softmax weights
// ---------------------------------------------------------------------------
__global__ void __launch_bounds__(256)
aggd_kernel(const float* __restrict__ depth_hypo) {
    int idx = blockIdx.x * blockDim.x + threadIdx.x;   // over B*D*HWSZ
    if (idx >= BB*DD*HWSZ) return;
    int pix = idx & (HWSZ-1);
    int x = pix & 127;
    int y = pix >> 7;
    int b = idx >> 19;

    const float* dsl = depth_hypo + (idx & ~(HWSZ-1));
    const float* csl = g_cost     + (idx & ~(HWSZ-1));
    const float* wfb = g_wfeat + (size_t)b*HWSZ + pix;

    float dc = dsl[pix];
    float esum = 0.0f, acc = 0.0f;

    #pragma unroll
    for (int k = 0; k < 25; k++) {
        int ny = y + k/5 - 2, nx = x + k%5 - 2;
        bool inb = (unsigned)ny < (unsigned)HH && (unsigned)nx < (unsigned)WW;
        int np = (ny<<7) + nx;
        float dn = inb ? dsl[np] : 0.0f;
        float e = __expf(fabsf(dn - dc));   // args in [0,~9]: no overflow
        esum += e;
        if (inb) {
            float cn = csl[np];
            float wf = wfb[(size_t)k * (BB*HWSZ)];
            acc += cn * e * wf;
        }
    }
    g_agg[idx] = __fdividef(acc, esum);
}

// ---------------------------------------------------------------------------
// K3c: softmax over D + depth expectation, per (b,pix)
// ---------------------------------------------------------------------------
__global__ void __launch_bounds__(128)
expect_kernel(const float* __restrict__ depth_hypo,
              float* __restrict__ out) {
    int idx = blockIdx.x * blockDim.x + threadIdx.x;   // over B*HWSZ
    if (idx >= BB*HWSZ) return;
    int pix = idx & (HWSZ-1);
    int b   = idx >> 14;

    const float* ab = g_agg      + (size_t)b*DD*HWSZ + pix;
    const float* db = depth_hypo + (size_t)b*DD*HWSZ + pix;

    float ag[DD], dv[DD];
    float m = -CUDART_INF_F;
    #pragma unroll
    for (int d = 0; d < DD; d++) {
        ag[d] = ab[(size_t)d*HWSZ];
        dv[d] = db[(size_t)d*HWSZ];
        m = fmaxf(m, ag[d]);
    }
    float ssum = 0.0f, tsum = 0.0f;
    #pragma unroll
    for (int d = 0; d < DD; d++) {
        float e = __expf(ag[d] - m);
        ssum += e;
        tsum += e * dv[d];
    }
    out[idx] = __fdividef(tsum, ssum);
}

// ---------------------------------------------------------------------------
extern "C" void kernel_launch(void* const* d_in, const int* in_sizes, int n_in,
                              void* d_out, int out_size) {
    const float* features   = (const float*)d_in[0];  // (3,2,16,128,128)
    const float* intrinsics = (const float*)d_in[1];  // (3,2,3,3)
    const float* cam2world  = (const float*)d_in[2];  // (3,2,4,4)
    const float* depth_hypo = (const float*)d_in[3];  // (2,32,128,128)
    float* out = (float*)d_out;                       // (2,128,128)

    proj_kernel<<<1, 32>>>(intrinsics, cam2world);

    {
        int n = VV*BB*HWSZ;
        nhwc_kernel<<<(n + 255)/256, 256>>>(features);
    }
    {
        int n = BB*DD*HWSZ;
        warp_cost_kernel<<<(n + 255)/256, 256>>>(depth_hypo);
    }
    {
        int n = 25*BB*HWSZ;
        wfeat_kernel<<<(n + 255)/256, 256>>>();
    }
    {
        int n = BB*DD*HWSZ;
        aggd_kernel<<<(n + 255)/256, 256>>>(depth_hypo);
    }
    {
        int n = BB*HWSZ;
        expect_kernel<<<(n + 127)/128, 128>>>(depth_hypo, out);
    }
}

// round 4
// speedup vs baseline: 1.5638x; 1.5638x over previous
#include <cuda_runtime.h>
#include <cuda_bf16.h>
#include <math_constants.h>

#define VV 3
#define BB 2
#define CC 16
#define HH 128
#define WW 128
#define DD 32
#define HWSZ (HH*WW)
#define NQ 4                       // 16 channels as 4 x float4 chunks

// Scratch (device globals; no runtime allocation)
__device__ float g_proj[(VV-1)*BB*12];
// channel-chunk-planar features: index (vb*NQ + q)*HWSZ + pix
__device__ float4 g_feat[(size_t)VV*BB*NQ*HWSZ];
__device__ float g_cost[(size_t)BB*DD*HWSZ];           // min cost volume (b,d,pix)
__device__ float g_wfeat[(size_t)25*BB*HWSZ];          // feature weights [k][b][pix]
__device__ float g_agg[(size_t)BB*DD*HWSZ];            // aggregated costs (b,d,pix)

// ---------------------------------------------------------------------------
// K0: projection matrices  proj = M_src @ inv(M_ref)
// ---------------------------------------------------------------------------
__device__ void mat3_inv_d(const double* A, double* o) {
    double c00 = A[4]*A[8]-A[5]*A[7];
    double c01 = A[5]*A[6]-A[3]*A[8];
    double c02 = A[3]*A[7]-A[4]*A[6];
    double det = A[0]*c00 + A[1]*c01 + A[2]*c02;
    double id = 1.0/det;
    o[0]=c00*id;                  o[1]=(A[2]*A[7]-A[1]*A[8])*id; o[2]=(A[1]*A[5]-A[2]*A[4])*id;
    o[3]=c01*id;                  o[4]=(A[0]*A[8]-A[2]*A[6])*id; o[5]=(A[2]*A[3]-A[0]*A[5])*id;
    o[6]=c02*id;                  o[7]=(A[1]*A[6]-A[0]*A[7])*id; o[8]=(A[0]*A[4]-A[1]*A[3])*id;
}

__device__ void build_M(const float* intr, const float* c2w, int vb,
                        double* Afull, double* bfull) {
    double K[9], R[9], t[3];
    #pragma unroll
    for (int i = 0; i < 3; i++) {
        #pragma unroll
        for (int j = 0; j < 3; j++) {
            K[i*3+j] = (double)intr[(vb*3+i)*3+j];
            R[i*3+j] = (double)c2w[(vb*4+i)*4+j];
        }
        t[i] = (double)c2w[(vb*4+i)*4+3];
    }
    double bb[3];
    #pragma unroll
    for (int i = 0; i < 3; i++)
        bb[i] = -(R[0*3+i]*t[0] + R[1*3+i]*t[1] + R[2*3+i]*t[2]);
    #pragma unroll
    for (int i = 0; i < 3; i++) {
        #pragma unroll
        for (int j = 0; j < 3; j++)
            Afull[i*3+j] = K[i*3+0]*R[j*3+0] + K[i*3+1]*R[j*3+1] + K[i*3+2]*R[j*3+2];
        bfull[i] = K[i*3+0]*bb[0] + K[i*3+1]*bb[1] + K[i*3+2]*bb[2] + bb[i];
    }
}

__global__ void proj_kernel(const float* __restrict__ intr,
                            const float* __restrict__ c2w) {
    int t = threadIdx.x;
    if (t >= (VV-1)*BB) return;
    int v = t / BB + 1;
    int b = t % BB;

    double As[9], bs[3], Ar[9], br[3];
    build_M(intr, c2w, v*BB + b, As, bs);
    build_M(intr, c2w, 0*BB + b, Ar, br);

    double Ainv[9];
    mat3_inv_d(Ar, Ainv);
    double binv[3];
    #pragma unroll
    for (int i = 0; i < 3; i++)
        binv[i] = -(Ainv[i*3+0]*br[0] + Ainv[i*3+1]*br[1] + Ainv[i*3+2]*br[2]);

    float* P = g_proj + t*12;
    #pragma unroll
    for (int i = 0; i < 3; i++) {
        #pragma unroll
        for (int j = 0; j < 3; j++)
            P[i*3+j] = (float)(As[i*3+0]*Ainv[0*3+j] + As[i*3+1]*Ainv[1*3+j] + As[i*3+2]*Ainv[2*3+j]);
        P[9+i] = (float)(As[i*3+0]*binv[0] + As[i*3+1]*binv[1] + As[i*3+2]*binv[2] + bs[i]);
    }
}

// ---------------------------------------------------------------------------
// K1: transpose features (V,B,C,H,W) -> chunk-planar (vb, q, pix) float4
// ---------------------------------------------------------------------------
__global__ void nhwc_kernel(const float* __restrict__ feat) {
    int idx = blockIdx.x * blockDim.x + threadIdx.x;
    if (idx >= VV*BB*HWSZ) return;
    int pix = idx & (HWSZ-1);
    int vb  = idx >> 14;
    const float* in = feat + (size_t)vb*CC*HWSZ + pix;
    #pragma unroll
    for (int q = 0; q < NQ; q++) {
        float4 v;
        v.x = in[(size_t)(q*4+0)*HWSZ];
        v.y = in[(size_t)(q*4+1)*HWSZ];
        v.z = in[(size_t)(q*4+2)*HWSZ];
        v.w = in[(size_t)(q*4+3)*HWSZ];
        g_feat[((size_t)(vb*NQ + q))*HWSZ + pix] = v;
    }
}

// ---------------------------------------------------------------------------
// K2: feature weights, smem-tiled. Block = 16x16 pixels, halo 20x20.
//     g_wfeat[k][b][pix] = ||f_nb - f_c|| (0 if neighbor OOB per zero-pad + safe_norm)
// ---------------------------------------------------------------------------
#define TS 16
#define THALO 20
__global__ void __launch_bounds__(256)
wfeat_kernel() {
    __shared__ float4 sf[NQ][THALO*THALO];

    int bx = blockIdx.x, by = blockIdx.y, b = blockIdx.z;
    int tid = threadIdx.x;
    int tx = tid & (TS-1), ty = tid >> 4;

    int ox = bx*TS - 2, oy = by*TS - 2;   // halo origin

    // load halo: 400 records, 256 threads
    for (int i = tid; i < THALO*THALO; i += 256) {
        int ly = i / THALO, lx = i - ly*THALO;
        int gy = oy + ly, gx = ox + lx;
        if ((unsigned)gy < (unsigned)HH && (unsigned)gx < (unsigned)WW) {
            int gp = (gy<<7) + gx;
            #pragma unroll
            for (int q = 0; q < NQ; q++)
                sf[q][i] = g_feat[((size_t)(b*NQ + q))*HWSZ + gp];
        }
    }
    __syncthreads();

    int x = bx*TS + tx, y = by*TS + ty;
    int pix = (y<<7) + x;
    int lc = (ty+2)*THALO + (tx+2);

    float fc[16];
    #pragma unroll
    for (int q = 0; q < NQ; q++) {
        float4 a = sf[q][lc];
        fc[q*4+0]=a.x; fc[q*4+1]=a.y; fc[q*4+2]=a.z; fc[q*4+3]=a.w;
    }

    #pragma unroll
    for (int k = 0; k < 25; k++) {
        int di = k/5, dj = k%5;
        int ny = y + di - 2, nx = x + dj - 2;
        float w = 0.0f;
        if ((unsigned)ny < (unsigned)HH && (unsigned)nx < (unsigned)WW) {
            int ln = (ty+di)*THALO + (tx+dj);
            float s = 0.0f;
            #pragma unroll
            for (int q = 0; q < NQ; q++) {
                float4 c = sf[q][ln];
                float d0 = fc[q*4+0]-c.x, d1 = fc[q*4+1]-c.y;
                float d2 = fc[q*4+2]-c.z, d3 = fc[q*4+3]-c.w;
                s += d0*d0 + d1*d1 + d2*d2 + d3*d3;
            }
            w = sqrtf(s);
        }
        g_wfeat[((size_t)k*BB + b)*HWSZ + pix] = w;
    }
}

// ---------------------------------------------------------------------------
// K3: homography warp + bilinear sample + cumsum cost + min over views
// ---------------------------------------------------------------------------
__global__ void __launch_bounds__(256)
warp_cost_kernel(const float* __restrict__ depth_hypo) {
    int idx = blockIdx.x * blockDim.x + threadIdx.x;
    if (idx >= BB*DD*HWSZ) return;
    int x = idx & 127;
    int y = (idx >> 7) & 127;
    int b = idx >> 19;
    int pix = idx & (HWSZ-1);

    float depth = depth_hypo[idx];

    float rv[16];
    #pragma unroll
    for (int q = 0; q < NQ; q++) {
        float4 r = g_feat[((size_t)(b*NQ + q))*HWSZ + pix];
        rv[q*4+0] = r.x; rv[q*4+1] = r.y; rv[q*4+2] = r.z; rv[q*4+3] = r.w;
    }

    float cum[16];
    #pragma unroll
    for (int c = 0; c < 16; c++) cum[c] = 0.0f;

    const float SXY = (float)WW / (float)(WW-1);
    float fxp = (float)x, fyp = (float)y;
    float cost_min = CUDART_INF_F;

    #pragma unroll
    for (int v = 0; v < VV-1; v++) {
        const float* P = g_proj + (v*BB + b)*12;
        float X = (P[0]*fxp + P[1]*fyp + P[2])*depth + P[9];
        float Y = (P[3]*fxp + P[4]*fyp + P[5])*depth + P[10];
        float Z = (P[6]*fxp + P[7]*fyp + P[8])*depth + P[11];
        float px = __fdividef(X, Z) * SXY - 0.5f;
        float py = __fdividef(Y, Z) * SXY - 0.5f;
        float x0f = floorf(px), y0f = floorf(py);
        float tx = px - x0f, ty = py - y0f;
        int x0 = (int)x0f, y0 = (int)y0f;

        float w00 = (1.0f-tx)*(1.0f-ty);
        float w01 = tx*(1.0f-ty);
        float w10 = (1.0f-tx)*ty;
        float w11 = tx*ty;

        int svb = (v+1)*BB + b;

        int xs[4] = {x0, x0+1, x0, x0+1};
        int ys[4] = {y0, y0, y0+1, y0+1};
        float ws[4] = {w00, w01, w10, w11};
        #pragma unroll
        for (int tap = 0; tap < 4; tap++) {
            int xi = xs[tap], yi = ys[tap];
            if ((unsigned)xi < (unsigned)WW && (unsigned)yi < (unsigned)HH) {
                int sp = (yi<<7) + xi;
                float w = ws[tap];
                #pragma unroll
                for (int q = 0; q < NQ; q++) {
                    float4 a = g_feat[((size_t)(svb*NQ + q))*HWSZ + sp];
                    cum[q*4+0] += w*a.x; cum[q*4+1] += w*a.y;
                    cum[q*4+2] += w*a.z; cum[q*4+3] += w*a.w;
                }
            }
        }

        float s = 0.0f;
        #pragma unroll
        for (int c = 0; c < 16; c++) {
            float dlt = rv[c] - cum[c];
            s += dlt*dlt;
        }
        cost_min = fminf(cost_min, sqrtf(s));
    }
    g_cost[idx] = cost_min;
}

// ---------------------------------------------------------------------------
// K4: aggregation, smem-tiled. Block = 16x16 pixels for one (b,d).
// ---------------------------------------------------------------------------
__global__ void __launch_bounds__(256)
aggd_kernel(const float* __restrict__ depth_hypo) {
    __shared__ float sd[THALO*THALO];
    __shared__ float sc[THALO*THALO];

    int bx = blockIdx.x, by = blockIdx.y, bd = blockIdx.z;  // bd over B*D
    int b = bd / DD;
    int tid = threadIdx.x;
    int tx = tid & (TS-1), ty = tid >> 4;

    const float* dsl = depth_hypo + (size_t)bd*HWSZ;
    const float* csl = g_cost     + (size_t)bd*HWSZ;

    int ox = bx*TS - 2, oy = by*TS - 2;
    for (int i = tid; i < THALO*THALO; i += 256) {
        int ly = i / THALO, lx = i - ly*THALO;
        int gy = oy + ly, gx = ox + lx;
        bool inb = (unsigned)gy < (unsigned)HH && (unsigned)gx < (unsigned)WW;
        int gp = (gy<<7) + gx;
        sd[i] = inb ? dsl[gp] : 0.0f;   // OOB depth = 0 (zero-pad semantics)
        sc[i] = inb ? csl[gp] : 0.0f;   // OOB cost unused but keep 0
    }
    __syncthreads();

    int x = bx*TS + tx, y = by*TS + ty;
    int pix = (y<<7) + x;

    float dc = sd[(ty+2)*THALO + (tx+2)];
    const float* wfb = g_wfeat + (size_t)b*HWSZ + pix;

    float esum = 0.0f, acc = 0.0f;
    #pragma unroll
    for (int k = 0; k < 25; k++) {
        int di = k/5, dj = k%5;
        int ny = y + di - 2, nx = x + dj - 2;
        bool inb = (unsigned)ny < (unsigned)HH && (unsigned)nx < (unsigned)WW;
        int ln = (ty+di)*THALO + (tx+dj);
        float dn = sd[ln];              // 0 when OOB (pre-zeroed)
        float e = __expf(fabsf(dn - dc));
        esum += e;
        if (inb) {
            float cn = sc[ln];
            float wf = wfb[(size_t)k * (BB*HWSZ)];
            acc += cn * e * wf;
        }
    }
    g_agg[(size_t)bd*HWSZ + pix] = __fdividef(acc, esum);
}

// ---------------------------------------------------------------------------
// K5: softmax over D + depth expectation, per (b,pix)
// ---------------------------------------------------------------------------
__global__ void __launch_bounds__(128)
expect_kernel(const float* __restrict__ depth_hypo,
              float* __restrict__ out) {
    int idx = blockIdx.x * blockDim.x + threadIdx.x;
    if (idx >= BB*HWSZ) return;
    int pix = idx & (HWSZ-1);
    int b   = idx >> 14;

    const float* ab = g_agg      + (size_t)b*DD*HWSZ + pix;
    const float* db = depth_hypo + (size_t)b*DD*HWSZ + pix;

    float ag[DD], dv[DD];
    float m = -CUDART_INF_F;
    #pragma unroll
    for (int d = 0; d < DD; d++) {
        ag[d] = ab[(size_t)d*HWSZ];
        dv[d] = db[(size_t)d*HWSZ];
        m = fmaxf(m, ag[d]);
    }
    float ssum = 0.0f, tsum = 0.0f;
    #pragma unroll
    for (int d = 0; d < DD; d++) {
        float e = __expf(ag[d] - m);
        ssum += e;
        tsum += e * dv[d];
    }
    out[idx] = __fdividef(tsum, ssum);
}

// ---------------------------------------------------------------------------
extern "C" void kernel_launch(void* const* d_in, const int* in_sizes, int n_in,
                              void* d_out, int out_size) {
    const float* features   = (const float*)d_in[0];  // (3,2,16,128,128)
    const float* intrinsics = (const float*)d_in[1];  // (3,2,3,3)
    const float* cam2world  = (const float*)d_in[2];  // (3,2,4,4)
    const float* depth_hypo = (const float*)d_in[3];  // (2,32,128,128)
    float* out = (float*)d_out;                       // (2,128,128)

    proj_kernel<<<1, 32>>>(intrinsics, cam2world);

    {
        int n = VV*BB*HWSZ;
        nhwc_kernel<<<(n + 255)/256, 256>>>(features);
    }
    {
        dim3 g(WW/TS, HH/TS, BB);
        wfeat_kernel<<<g, 256>>>();
    }
    {
        int n = BB*DD*HWSZ;
        warp_cost_kernel<<<(n + 255)/256, 256>>>(depth_hypo);
    }
    {
        dim3 g(WW/TS, HH/TS, BB*DD);
        aggd_kernel<<<g, 256>>>(depth_hypo);
    }
    {
        int n = BB*HWSZ;
        expect_kernel<<<(n + 127)/128, 128>>>(depth_hypo, out);
    }
}